// round 1
// baseline (speedup 1.0000x reference)
#include <cuda_runtime.h>
#include <math.h>

// MoE top-2-of-8: T=8192 tokens, D=1024, H=2048, E=8, fp32.
// Pipeline: zero -> router(top2 gather) -> gathered gate/up GEMM + SiLU -> down GEMM + weighted scatter.

#define NT 8192
#define DD 1024
#define HH 2048
#define NE 8

// Device scratch (allocation-free rule: __device__ globals).
__device__ int   g_count[NE];
__device__ int   g_tok[NE][NT];
__device__ float g_wt[NE][NT];
__device__ float g_act[(size_t)NE * NT * HH];   // 512 MB activation scratch

// ---------------------------------------------------------------------------
// Zero output + counters
// ---------------------------------------------------------------------------
__global__ void k_zero(float* __restrict__ out) {
    int i = blockIdx.x * blockDim.x + threadIdx.x;
    float4 z = make_float4(0.f, 0.f, 0.f, 0.f);
    if (i < (NT * DD / 4)) reinterpret_cast<float4*>(out)[i] = z;
    if (i < NE) g_count[i] = 0;
}

// ---------------------------------------------------------------------------
// Router: warp per token. logits = x @ router_w^T, renormalized top-2.
// ---------------------------------------------------------------------------
__global__ void k_router(const float* __restrict__ x, const float* __restrict__ rw) {
    __shared__ float s_rw[NE * DD];
    const int tid = threadIdx.x;
    for (int i = tid; i < NE * DD; i += 256) s_rw[i] = rw[i];
    __syncthreads();

    const int warp = tid >> 5;
    const int lane = tid & 31;
    const int token = blockIdx.x * 8 + warp;
    const float* xr = x + (size_t)token * DD;

    float acc[NE];
#pragma unroll
    for (int e = 0; e < NE; e++) acc[e] = 0.f;

    for (int d = lane; d < DD; d += 32) {
        float xv = xr[d];
#pragma unroll
        for (int e = 0; e < NE; e++) acc[e] = fmaf(xv, s_rw[e * DD + d], acc[e]);
    }
#pragma unroll
    for (int e = 0; e < NE; e++) {
#pragma unroll
        for (int off = 16; off > 0; off >>= 1)
            acc[e] += __shfl_xor_sync(0xffffffffu, acc[e], off);
    }

    if (lane == 0) {
        int i1 = 0;
#pragma unroll
        for (int e = 1; e < NE; e++) if (acc[e] > acc[i1]) i1 = e;
        int i2 = (i1 == 0) ? 1 : 0;
#pragma unroll
        for (int e = 0; e < NE; e++) if (e != i1 && acc[e] > acc[i2]) i2 = e;
        // Renormalized top-2 softmax == 2-way softmax over {l1, l2}.
        float s  = expf(acc[i2] - acc[i1]);
        float p1 = 1.f / (1.f + s);
        float p2 = s / (1.f + s);
        int s1 = atomicAdd(&g_count[i1], 1);
        g_tok[i1][s1] = token; g_wt[i1][s1] = p1;
        int s2 = atomicAdd(&g_count[i2], 1);
        g_tok[i2][s2] = token; g_wt[i2][s2] = p2;
    }
}

// ---------------------------------------------------------------------------
// Gate + Up fused GEMM with gather:  act = silu(Xg @ Wg^T) * (Xg @ Wu^T)
// Block tile: 128 rows x 64 cols (per matrix), BK=16, 256 threads, 8x4(+8x4)/thread.
// ---------------------------------------------------------------------------
__global__ __launch_bounds__(256, 2) void k_gateup(
    const float* __restrict__ x,
    const float* __restrict__ gw,
    const float* __restrict__ uw) {
    const int e  = blockIdx.z;
    const int ne = g_count[e];
    const int m0 = blockIdx.y * 128;
    if (m0 >= ne) return;
    const int n0 = blockIdx.x * 64;

    __shared__ float As[16][132];
    __shared__ float Bg[16][68];
    __shared__ float Bu[16][68];

    const int tid = threadIdx.x;

    // A loader: 2 threads per row, 8 floats each
    const int arow = tid >> 1;
    const int akq  = (tid & 1) << 3;             // float offset 0 or 8
    int grow = m0 + arow;
    if (grow >= ne) grow = ne - 1;               // clamp: padded rows compute garbage, never read validly
    const float* aptr = x + (size_t)g_tok[e][grow] * DD + akq;

    // B loaders: 4 threads per row, 4 floats each
    const int brow = tid >> 2;
    const int bko  = (tid & 3) << 2;             // float offset 0,4,8,12
    const size_t wbase = (size_t)e * HH * DD + (size_t)(n0 + brow) * DD + bko;
    const float* gptr = gw + wbase;
    const float* uptr = uw + wbase;

    const int tx = tid & 15;
    const int ty = tid >> 4;

    float accg[8][4], accu[8][4];
#pragma unroll
    for (int i = 0; i < 8; i++)
#pragma unroll
        for (int j = 0; j < 4; j++) { accg[i][j] = 0.f; accu[i][j] = 0.f; }

    for (int k0 = 0; k0 < DD; k0 += 16) {
        float4 a0v = *reinterpret_cast<const float4*>(aptr + k0);
        float4 a1v = *reinterpret_cast<const float4*>(aptr + k0 + 4);
        float4 bgv = *reinterpret_cast<const float4*>(gptr + k0);
        float4 buv = *reinterpret_cast<const float4*>(uptr + k0);
        __syncthreads();
        As[akq + 0][arow] = a0v.x; As[akq + 1][arow] = a0v.y;
        As[akq + 2][arow] = a0v.z; As[akq + 3][arow] = a0v.w;
        As[akq + 4][arow] = a1v.x; As[akq + 5][arow] = a1v.y;
        As[akq + 6][arow] = a1v.z; As[akq + 7][arow] = a1v.w;
        Bg[bko + 0][brow] = bgv.x; Bg[bko + 1][brow] = bgv.y;
        Bg[bko + 2][brow] = bgv.z; Bg[bko + 3][brow] = bgv.w;
        Bu[bko + 0][brow] = buv.x; Bu[bko + 1][brow] = buv.y;
        Bu[bko + 2][brow] = buv.z; Bu[bko + 3][brow] = buv.w;
        __syncthreads();
#pragma unroll
        for (int kk = 0; kk < 16; kk++) {
            float4 av0 = *reinterpret_cast<const float4*>(&As[kk][ty * 8]);
            float4 av1 = *reinterpret_cast<const float4*>(&As[kk][ty * 8 + 4]);
            float4 bg4 = *reinterpret_cast<const float4*>(&Bg[kk][tx * 4]);
            float4 bu4 = *reinterpret_cast<const float4*>(&Bu[kk][tx * 4]);
            float am[8] = {av0.x, av0.y, av0.z, av0.w, av1.x, av1.y, av1.z, av1.w};
            float bgA[4] = {bg4.x, bg4.y, bg4.z, bg4.w};
            float buA[4] = {bu4.x, bu4.y, bu4.z, bu4.w};
#pragma unroll
            for (int i = 0; i < 8; i++) {
#pragma unroll
                for (int j = 0; j < 4; j++) {
                    accg[i][j] = fmaf(am[i], bgA[j], accg[i][j]);
                    accu[i][j] = fmaf(am[i], buA[j], accu[i][j]);
                }
            }
        }
    }

    // Epilogue: silu(gate) * up -> scratch
    float* actbase = g_act + (size_t)e * NT * HH + (size_t)m0 * HH + n0 + tx * 4;
#pragma unroll
    for (int i = 0; i < 8; i++) {
        const int mrow = ty * 8 + i;
        float4 v;
        v.x = (accg[i][0] / (1.f + expf(-accg[i][0]))) * accu[i][0];
        v.y = (accg[i][1] / (1.f + expf(-accg[i][1]))) * accu[i][1];
        v.z = (accg[i][2] / (1.f + expf(-accg[i][2]))) * accu[i][2];
        v.w = (accg[i][3] / (1.f + expf(-accg[i][3]))) * accu[i][3];
        *reinterpret_cast<float4*>(actbase + (size_t)mrow * HH) = v;
    }
}

// ---------------------------------------------------------------------------
// Down GEMM + weighted scatter:  out[tok] += w * (act @ Wd^T)
// Block tile: 128 x 128, BK=16, 256 threads, 8x8/thread.
// ---------------------------------------------------------------------------
__global__ __launch_bounds__(256, 2) void k_down(
    const float* __restrict__ dw, float* __restrict__ out) {
    const int e  = blockIdx.z;
    const int ne = g_count[e];
    const int m0 = blockIdx.y * 128;
    if (m0 >= ne) return;
    const int n0 = blockIdx.x * 128;

    __shared__ float As[16][132];
    __shared__ float Bs[16][132];

    const int tid = threadIdx.x;
    const int arow = tid >> 1;
    const int akq  = (tid & 1) << 3;
    const float* aptr = g_act + (size_t)e * NT * HH + (size_t)(m0 + arow) * HH + akq;
    const float* bptr = dw + (size_t)e * DD * HH + (size_t)(n0 + arow) * HH + akq;

    const int tx = tid & 15;
    const int ty = tid >> 4;

    float acc[8][8];
#pragma unroll
    for (int i = 0; i < 8; i++)
#pragma unroll
        for (int j = 0; j < 8; j++) acc[i][j] = 0.f;

    for (int k0 = 0; k0 < HH; k0 += 16) {
        float4 a0v = *reinterpret_cast<const float4*>(aptr + k0);
        float4 a1v = *reinterpret_cast<const float4*>(aptr + k0 + 4);
        float4 b0v = *reinterpret_cast<const float4*>(bptr + k0);
        float4 b1v = *reinterpret_cast<const float4*>(bptr + k0 + 4);
        __syncthreads();
        As[akq + 0][arow] = a0v.x; As[akq + 1][arow] = a0v.y;
        As[akq + 2][arow] = a0v.z; As[akq + 3][arow] = a0v.w;
        As[akq + 4][arow] = a1v.x; As[akq + 5][arow] = a1v.y;
        As[akq + 6][arow] = a1v.z; As[akq + 7][arow] = a1v.w;
        Bs[akq + 0][arow] = b0v.x; Bs[akq + 1][arow] = b0v.y;
        Bs[akq + 2][arow] = b0v.z; Bs[akq + 3][arow] = b0v.w;
        Bs[akq + 4][arow] = b1v.x; Bs[akq + 5][arow] = b1v.y;
        Bs[akq + 6][arow] = b1v.z; Bs[akq + 7][arow] = b1v.w;
        __syncthreads();
#pragma unroll
        for (int kk = 0; kk < 16; kk++) {
            float4 av0 = *reinterpret_cast<const float4*>(&As[kk][ty * 8]);
            float4 av1 = *reinterpret_cast<const float4*>(&As[kk][ty * 8 + 4]);
            float4 bv0 = *reinterpret_cast<const float4*>(&Bs[kk][tx * 8]);
            float4 bv1 = *reinterpret_cast<const float4*>(&Bs[kk][tx * 8 + 4]);
            float am[8] = {av0.x, av0.y, av0.z, av0.w, av1.x, av1.y, av1.z, av1.w};
            float bm[8] = {bv0.x, bv0.y, bv0.z, bv0.w, bv1.x, bv1.y, bv1.z, bv1.w};
#pragma unroll
            for (int i = 0; i < 8; i++)
#pragma unroll
                for (int j = 0; j < 8; j++)
                    acc[i][j] = fmaf(am[i], bm[j], acc[i][j]);
        }
    }

    // Epilogue: weighted atomic scatter (each out element touched by exactly 2
    // experts -> commutative float adds, deterministic).
#pragma unroll
    for (int i = 0; i < 8; i++) {
        const int m = m0 + ty * 8 + i;
        if (m < ne) {
            const int   tokn = g_tok[e][m];
            const float w    = g_wt[e][m];
            float* op = out + (size_t)tokn * DD + n0 + tx * 8;
#pragma unroll
            for (int j = 0; j < 8; j++) atomicAdd(op + j, w * acc[i][j]);
        }
    }
}

// ---------------------------------------------------------------------------
extern "C" void kernel_launch(void* const* d_in, const int* in_sizes, int n_in,
                              void* d_out, int out_size) {
    const float* x  = (const float*)d_in[0];  // [4,2048,1024]
    const float* rw = (const float*)d_in[1];  // [8,1024]
    const float* gw = (const float*)d_in[2];  // [8,2048,1024]
    const float* uw = (const float*)d_in[3];  // [8,2048,1024]
    const float* dw = (const float*)d_in[4];  // [8,1024,2048]
    float* out = (float*)d_out;               // [4,2048,1024]

    k_zero<<<(NT * DD / 4 + 255) / 256, 256>>>(out);
    k_router<<<NT / 8, 256>>>(x, rw);
    k_gateup<<<dim3(HH / 64, NT / 128, NE), 256>>>(x, gw, uw);
    k_down<<<dim3(DD / 128, NT / 128, NE), 256>>>(dw, out);
}

// round 6
// speedup vs baseline: 3.0339x; 3.0339x over previous
#include <cuda_runtime.h>
#include <cstdint>
#include <math.h>

// MoE top-2-of-8: T=8192, D=1024, H=2048, fp32 in/out.
// zero -> router(fp32 exact top2) -> tf32 mma.sync gate/up GEMM + SiLU -> tf32 mma.sync down GEMM + weighted scatter.
// NOTE: harness compiles via compute_103 (no 'a' features) -> tcgen05 unavailable; use legacy mma.sync path.

#define NT 8192
#define DD 1024
#define HH 2048
#define NE 8

__device__ int   g_count[NE];
__device__ int   g_tok[NE][NT];
__device__ float g_wt[NE][NT];
__device__ float g_act[(size_t)NE * NT * HH];   // 512 MB activation scratch

// ---------------------------------------------------------------------------
// Helpers (all plain compute_80/90 features)
// ---------------------------------------------------------------------------
__device__ __forceinline__ uint32_t smem_u32(const void* p) {
    uint32_t a;
    asm("{ .reg .u64 t; cvta.to.shared.u64 t, %1; cvt.u32.u64 %0, t; }" : "=r"(a) : "l"(p));
    return a;
}
__device__ __forceinline__ uint32_t f2tf(uint32_t r) {   // round-to-nearest tf32
    uint32_t u;
    asm("cvt.rna.tf32.f32 %0, %1;" : "=r"(u) : "f"(__uint_as_float(r)));
    return u;
}
#define CPA(dst, src) asm volatile("cp.async.cg.shared.global [%0], [%1], 16;" :: "r"(dst), "l"(src))
#define CPC()         asm volatile("cp.async.commit_group;" ::: "memory")
#define CPW(n)        asm volatile("cp.async.wait_group %0;" :: "n"(n) : "memory")

__device__ __forceinline__ void ldsm4(uint32_t& r0, uint32_t& r1, uint32_t& r2, uint32_t& r3, uint32_t a) {
    asm volatile("ldmatrix.sync.aligned.m8n8.x4.shared.b16 {%0,%1,%2,%3}, [%4];"
                 : "=r"(r0), "=r"(r1), "=r"(r2), "=r"(r3) : "r"(a));
}
__device__ __forceinline__ void mma8(float* c, const uint32_t* a, const uint32_t* b) {
    asm volatile("mma.sync.aligned.m16n8k8.row.col.f32.tf32.tf32.f32 "
                 "{%0,%1,%2,%3}, {%4,%5,%6,%7}, {%8,%9}, {%0,%1,%2,%3};"
                 : "+f"(c[0]), "+f"(c[1]), "+f"(c[2]), "+f"(c[3])
                 : "r"(a[0]), "r"(a[1]), "r"(a[2]), "r"(a[3]), "r"(b[0]), "r"(b[1]));
}

// ---------------------------------------------------------------------------
__global__ void k_zero(float* __restrict__ out) {
    int i = blockIdx.x * blockDim.x + threadIdx.x;
    float4 z = make_float4(0.f, 0.f, 0.f, 0.f);
    if (i < (NT * DD / 4)) reinterpret_cast<float4*>(out)[i] = z;
    if (i < NE) g_count[i] = 0;
}

// ---------------------------------------------------------------------------
// Router (exact fp32): warp per token, renormalized top-2, scatter.
// ---------------------------------------------------------------------------
__global__ void k_router(const float* __restrict__ x, const float* __restrict__ rw) {
    __shared__ float s_rw[NE * DD];
    const int tid = threadIdx.x;
    for (int i = tid; i < NE * DD; i += 256) s_rw[i] = rw[i];
    __syncthreads();

    const int warp = tid >> 5;
    const int lane = tid & 31;
    const int token = blockIdx.x * 8 + warp;
    const float* xr = x + (size_t)token * DD;

    float acc[NE];
#pragma unroll
    for (int e = 0; e < NE; e++) acc[e] = 0.f;
    for (int d = lane; d < DD; d += 32) {
        float xv = xr[d];
#pragma unroll
        for (int e = 0; e < NE; e++) acc[e] = fmaf(xv, s_rw[e * DD + d], acc[e]);
    }
#pragma unroll
    for (int e = 0; e < NE; e++)
#pragma unroll
        for (int off = 16; off > 0; off >>= 1)
            acc[e] += __shfl_xor_sync(0xffffffffu, acc[e], off);

    if (lane == 0) {
        int i1 = 0;
#pragma unroll
        for (int e = 1; e < NE; e++) if (acc[e] > acc[i1]) i1 = e;
        int i2 = (i1 == 0) ? 1 : 0;
#pragma unroll
        for (int e = 0; e < NE; e++) if (e != i1 && acc[e] > acc[i2]) i2 = e;
        float s  = expf(acc[i2] - acc[i1]);
        float p1 = 1.f / (1.f + s);
        float p2 = s / (1.f + s);
        int s1 = atomicAdd(&g_count[i1], 1);
        g_tok[i1][s1] = token; g_wt[i1][s1] = p1;
        int s2 = atomicAdd(&g_count[i2], 1);
        g_tok[i2][s2] = token; g_wt[i2][s2] = p2;
    }
}

// ---------------------------------------------------------------------------
// Gate+Up tf32 GEMM: block 128(M) x 64(N), both gate & up on same N columns.
// 8 warps: wid<4 gate, wid>=4 up; warp tile 64x32 (2x2 grid). BK=32, cp.async x2.
// smem rows padded to stride 36 floats (conflict-free ldmatrix + STS).
// ---------------------------------------------------------------------------
#define SA 36
#define GU_AFL (128 * SA)
#define GU_BFL (64 * SA)
#define GU_STG (GU_AFL + 2 * GU_BFL)
#define GU_SMEMB (2 * GU_STG * 4)

__global__ __launch_bounds__(256) void k_gateup(
    const float* __restrict__ x, const float* __restrict__ gw, const float* __restrict__ uw) {
    const int e  = blockIdx.z;
    const int ne = g_count[e];
    const int m0 = blockIdx.y * 128;
    if (m0 >= ne) return;
    const int n0 = blockIdx.x * 64;

    extern __shared__ float sm[];
    const uint32_t sbase = smem_u32(sm);
    const int tid = threadIdx.x, lane = tid & 31, wid = tid >> 5;
    const int half = wid >> 2, wq = wid & 3;
    const int wm = (wq >> 1) * 64, wn = (wq & 1) * 32;

    // Loaders: A = 128 rows x 8 16B-chunks -> 4/thread; Bg,Bu = 64x8 -> 2/thread each.
    const float* asrc[4]; uint32_t adst[4];
#pragma unroll
    for (int i = 0; i < 4; i++) {
        int c = i * 256 + tid, row = c >> 3, kc = c & 7;
        int gr = m0 + row; if (gr >= ne) gr = ne - 1;   // clamp; padded rows discarded downstream
        asrc[i] = x + (size_t)g_tok[e][gr] * DD + kc * 4;
        adst[i] = (uint32_t)(row * SA + kc * 4) * 4u;
    }
    const float *gsrc[2], *usrc[2]; uint32_t bdst[2];
#pragma unroll
    for (int i = 0; i < 2; i++) {
        int c = i * 256 + tid, row = c >> 3, kc = c & 7;
        size_t off = (size_t)e * HH * DD + (size_t)(n0 + row) * DD + kc * 4;
        gsrc[i] = gw + off; usrc[i] = uw + off;
        bdst[i] = (uint32_t)(row * SA + kc * 4) * 4u;
    }

#define GU_LOAD(buf, kt) do {                                                   \
        uint32_t s0 = sbase + (uint32_t)(buf) * (GU_STG * 4);                   \
        _Pragma("unroll")                                                       \
        for (int i = 0; i < 4; i++) CPA(s0 + adst[i], asrc[i] + (kt) * 32);     \
        _Pragma("unroll")                                                       \
        for (int i = 0; i < 2; i++) {                                           \
            CPA(s0 + GU_AFL * 4 + bdst[i], gsrc[i] + (kt) * 32);                \
            CPA(s0 + (GU_AFL + GU_BFL) * 4 + bdst[i], usrc[i] + (kt) * 32);     \
        }                                                                       \
    } while (0)

    float acc[4][4][4];
#pragma unroll
    for (int mi = 0; mi < 4; mi++)
#pragma unroll
        for (int nj = 0; nj < 4; nj++)
#pragma unroll
            for (int r = 0; r < 4; r++) acc[mi][nj][r] = 0.f;

    const uint32_t a_lrow = lane & 15;
    const uint32_t a_lcol = ((lane >> 4) & 1) * 4;
    const uint32_t b_lrow = (lane & 7) + ((lane >> 4) & 1) * 8;
    const uint32_t b_lcol = ((lane >> 3) & 1) * 4;

    GU_LOAD(0, 0);
    CPC();
    const int NK = DD / 32;
    for (int t = 0; t < NK; t++) {
        if (t + 1 < NK) { GU_LOAD((t + 1) & 1, t + 1); CPC(); CPW(1); }
        else            { CPW(0); }
        __syncthreads();
        const uint32_t sAq = sbase + (uint32_t)(t & 1) * (GU_STG * 4);
        const uint32_t sBq = sAq + (uint32_t)(GU_AFL + half * GU_BFL) * 4;
#pragma unroll
        for (int k8 = 0; k8 < 32; k8 += 8) {
            uint32_t a[4][4], b[4][2];
#pragma unroll
            for (int mi = 0; mi < 4; mi++)
                ldsm4(a[mi][0], a[mi][1], a[mi][2], a[mi][3],
                      sAq + ((wm + mi * 16 + a_lrow) * SA + a_lcol + k8) * 4);
#pragma unroll
            for (int p = 0; p < 2; p++) {
                uint32_t r0, r1, r2, r3;
                ldsm4(r0, r1, r2, r3,
                      sBq + ((wn + p * 16 + b_lrow) * SA + b_lcol + k8) * 4);
                b[2 * p][0] = r0; b[2 * p][1] = r1; b[2 * p + 1][0] = r2; b[2 * p + 1][1] = r3;
            }
#pragma unroll
            for (int mi = 0; mi < 4; mi++)
#pragma unroll
                for (int j = 0; j < 4; j++) a[mi][j] = f2tf(a[mi][j]);
#pragma unroll
            for (int nj = 0; nj < 4; nj++) { b[nj][0] = f2tf(b[nj][0]); b[nj][1] = f2tf(b[nj][1]); }
#pragma unroll
            for (int mi = 0; mi < 4; mi++)
#pragma unroll
                for (int nj = 0; nj < 4; nj++) mma8(acc[mi][nj], a[mi], b[nj]);
        }
        __syncthreads();
    }
#undef GU_LOAD

    // Epilogue: up warps stage accum in smem; gate warps combine silu(g)*u -> g_act.
    if (half == 1) {
#pragma unroll
        for (int mi = 0; mi < 4; mi++)
#pragma unroll
            for (int nj = 0; nj < 4; nj++) {
                int m = wm + mi * 16 + (lane >> 2);
                int n = wn + nj * 8 + (lane & 3) * 2;
                *(float2*)&sm[m * 66 + n]       = make_float2(acc[mi][nj][0], acc[mi][nj][1]);
                *(float2*)&sm[(m + 8) * 66 + n] = make_float2(acc[mi][nj][2], acc[mi][nj][3]);
            }
    }
    __syncthreads();
    if (half == 0) {
        float* actb = g_act + (size_t)e * NT * HH + (size_t)m0 * HH + n0;
#pragma unroll
        for (int mi = 0; mi < 4; mi++)
#pragma unroll
            for (int nj = 0; nj < 4; nj++) {
                int m = wm + mi * 16 + (lane >> 2);
                int n = wn + nj * 8 + (lane & 3) * 2;
                float2 u0 = *(float2*)&sm[m * 66 + n];
                float2 u1 = *(float2*)&sm[(m + 8) * 66 + n];
                float g0 = acc[mi][nj][0], g1 = acc[mi][nj][1];
                float g2 = acc[mi][nj][2], g3 = acc[mi][nj][3];
                float2 v0, v1;
                v0.x = g0 / (1.f + expf(-g0)) * u0.x;
                v0.y = g1 / (1.f + expf(-g1)) * u0.y;
                v1.x = g2 / (1.f + expf(-g2)) * u1.x;
                v1.y = g3 / (1.f + expf(-g3)) * u1.y;
                *(float2*)(actb + (size_t)m * HH + n)       = v0;
                *(float2*)(actb + (size_t)(m + 8) * HH + n) = v1;
            }
    }
}

// ---------------------------------------------------------------------------
// Down tf32 GEMM + weighted scatter: block 128(M) x 128(N), 8 warps 2x4, warp 64x32.
// ---------------------------------------------------------------------------
#define DN_AFL (128 * SA)
#define DN_STG (2 * DN_AFL)
#define DN_SMEMB (2 * DN_STG * 4)

__global__ __launch_bounds__(256) void k_down(
    const float* __restrict__ dw, float* __restrict__ out) {
    const int e  = blockIdx.z;
    const int ne = g_count[e];
    const int m0 = blockIdx.y * 128;
    if (m0 >= ne) return;
    const int n0 = blockIdx.x * 128;

    extern __shared__ float sm[];
    const uint32_t sbase = smem_u32(sm);
    const int tid = threadIdx.x, lane = tid & 31, wid = tid >> 5;
    const int wm = (wid >> 2) * 64, wn = (wid & 3) * 32;

    const float *asrc[4], *bsrc[4]; uint32_t cdst[4];
#pragma unroll
    for (int i = 0; i < 4; i++) {
        int c = i * 256 + tid, row = c >> 3, kc = c & 7;
        asrc[i] = g_act + (size_t)e * NT * HH + (size_t)(m0 + row) * HH + kc * 4;
        bsrc[i] = dw + (size_t)e * DD * HH + (size_t)(n0 + row) * HH + kc * 4;
        cdst[i] = (uint32_t)(row * SA + kc * 4) * 4u;
    }

#define DN_LOAD(buf, kt) do {                                                   \
        uint32_t s0 = sbase + (uint32_t)(buf) * (DN_STG * 4);                   \
        _Pragma("unroll")                                                       \
        for (int i = 0; i < 4; i++) {                                           \
            CPA(s0 + cdst[i], asrc[i] + (kt) * 32);                             \
            CPA(s0 + DN_AFL * 4 + cdst[i], bsrc[i] + (kt) * 32);                \
        }                                                                       \
    } while (0)

    float acc[4][4][4];
#pragma unroll
    for (int mi = 0; mi < 4; mi++)
#pragma unroll
        for (int nj = 0; nj < 4; nj++)
#pragma unroll
            for (int r = 0; r < 4; r++) acc[mi][nj][r] = 0.f;

    const uint32_t a_lrow = lane & 15;
    const uint32_t a_lcol = ((lane >> 4) & 1) * 4;
    const uint32_t b_lrow = (lane & 7) + ((lane >> 4) & 1) * 8;
    const uint32_t b_lcol = ((lane >> 3) & 1) * 4;

    DN_LOAD(0, 0);
    CPC();
    const int NK = HH / 32;
    for (int t = 0; t < NK; t++) {
        if (t + 1 < NK) { DN_LOAD((t + 1) & 1, t + 1); CPC(); CPW(1); }
        else            { CPW(0); }
        __syncthreads();
        const uint32_t sAq = sbase + (uint32_t)(t & 1) * (DN_STG * 4);
        const uint32_t sBq = sAq + DN_AFL * 4;
#pragma unroll
        for (int k8 = 0; k8 < 32; k8 += 8) {
            uint32_t a[4][4], b[4][2];
#pragma unroll
            for (int mi = 0; mi < 4; mi++)
                ldsm4(a[mi][0], a[mi][1], a[mi][2], a[mi][3],
                      sAq + ((wm + mi * 16 + a_lrow) * SA + a_lcol + k8) * 4);
#pragma unroll
            for (int p = 0; p < 2; p++) {
                uint32_t r0, r1, r2, r3;
                ldsm4(r0, r1, r2, r3,
                      sBq + ((wn + p * 16 + b_lrow) * SA + b_lcol + k8) * 4);
                b[2 * p][0] = r0; b[2 * p][1] = r1; b[2 * p + 1][0] = r2; b[2 * p + 1][1] = r3;
            }
#pragma unroll
            for (int mi = 0; mi < 4; mi++)
#pragma unroll
                for (int j = 0; j < 4; j++) a[mi][j] = f2tf(a[mi][j]);
#pragma unroll
            for (int nj = 0; nj < 4; nj++) { b[nj][0] = f2tf(b[nj][0]); b[nj][1] = f2tf(b[nj][1]); }
#pragma unroll
            for (int mi = 0; mi < 4; mi++)
#pragma unroll
                for (int nj = 0; nj < 4; nj++) mma8(acc[mi][nj], a[mi], b[nj]);
        }
        __syncthreads();
    }
#undef DN_LOAD

    // Weighted atomic scatter (each out element gets exactly 2 commutative adds).
#pragma unroll
    for (int mi = 0; mi < 4; mi++) {
        int mg0 = m0 + wm + mi * 16 + (lane >> 2);
        int mg1 = mg0 + 8;
        bool v0 = mg0 < ne, v1 = mg1 < ne;
        int   t0 = v0 ? g_tok[e][mg0] : 0;  float w0 = v0 ? g_wt[e][mg0] : 0.f;
        int   t1 = v1 ? g_tok[e][mg1] : 0;  float w1 = v1 ? g_wt[e][mg1] : 0.f;
        float* r0p = out + (size_t)t0 * DD;
        float* r1p = out + (size_t)t1 * DD;
#pragma unroll
        for (int nj = 0; nj < 4; nj++) {
            int n = n0 + wn + nj * 8 + (lane & 3) * 2;
            if (v0) {
                atomicAdd(r0p + n,     w0 * acc[mi][nj][0]);
                atomicAdd(r0p + n + 1, w0 * acc[mi][nj][1]);
            }
            if (v1) {
                atomicAdd(r1p + n,     w1 * acc[mi][nj][2]);
                atomicAdd(r1p + n + 1, w1 * acc[mi][nj][3]);
            }
        }
    }
}

// ---------------------------------------------------------------------------
extern "C" void kernel_launch(void* const* d_in, const int* in_sizes, int n_in,
                              void* d_out, int out_size) {
    const float* x  = (const float*)d_in[0];  // [4,2048,1024]
    const float* rw = (const float*)d_in[1];  // [8,1024]
    const float* gw = (const float*)d_in[2];  // [8,2048,1024]
    const float* uw = (const float*)d_in[3];  // [8,2048,1024]
    const float* dw = (const float*)d_in[4];  // [8,1024,2048]
    float* out = (float*)d_out;               // [4,2048,1024]

    cudaFuncSetAttribute(k_gateup, cudaFuncAttributeMaxDynamicSharedMemorySize, GU_SMEMB);
    cudaFuncSetAttribute(k_down,   cudaFuncAttributeMaxDynamicSharedMemorySize, DN_SMEMB);

    k_zero<<<(NT * DD / 4 + 255) / 256, 256>>>(out);
    k_router<<<NT / 8, 256>>>(x, rw);
    k_gateup<<<dim3(HH / 64, NT / 128, NE), 256, GU_SMEMB>>>(x, gw, uw);
    k_down<<<dim3(DD / 128, NT / 128, NE), 256, DN_SMEMB>>>(dw, out);
}

// round 15
// speedup vs baseline: 5.1155x; 1.6861x over previous
#include <cuda_runtime.h>
#include <cuda_fp16.h>
#include <cstdint>
#include <math.h>

// MoE top-2-of-8: T=8192, D=1024, H=2048, fp32 in/out.
// converts(fp32->fp16) -> router(fp32 exact top2) -> fp16 mma gate/up + SiLU -> fp16 mma down + weighted scatter.
// fp16 mantissa (11 bit significand) == tf32 mantissa, at 2x rate and half the traffic.

#define NT 8192
#define DD 1024
#define HH 2048
#define NE 8

__device__ int    g_count[NE];
__device__ int    g_tok[NE][NT];
__device__ float  g_wt[NE][NT];
__device__ __half g_xh[(size_t)NT * DD];            // 16 MB
__device__ __half g_wgh[(size_t)NE * HH * DD];      // 33.5 MB
__device__ __half g_wuh[(size_t)NE * HH * DD];      // 33.5 MB
__device__ __half g_wdh[(size_t)NE * DD * HH];      // 33.5 MB
__device__ __half g_acth[(size_t)NE * NT * HH];     // 268 MB

// ---------------------------------------------------------------------------
__device__ __forceinline__ uint32_t smem_u32(const void* p) {
    uint32_t a;
    asm("{ .reg .u64 t; cvta.to.shared.u64 t, %1; cvt.u32.u64 %0, t; }" : "=r"(a) : "l"(p));
    return a;
}
#define CPA(dst, src) asm volatile("cp.async.cg.shared.global [%0], [%1], 16;" :: "r"(dst), "l"(src))
#define CPC()         asm volatile("cp.async.commit_group;" ::: "memory")
#define CPW(n)        asm volatile("cp.async.wait_group %0;" :: "n"(n) : "memory")

__device__ __forceinline__ void ldsm4(uint32_t& r0, uint32_t& r1, uint32_t& r2, uint32_t& r3, uint32_t a) {
    asm volatile("ldmatrix.sync.aligned.m8n8.x4.shared.b16 {%0,%1,%2,%3}, [%4];"
                 : "=r"(r0), "=r"(r1), "=r"(r2), "=r"(r3) : "r"(a));
}
__device__ __forceinline__ void mma16(float* c, const uint32_t* a, const uint32_t* b) {
    asm volatile("mma.sync.aligned.m16n8k16.row.col.f32.f16.f16.f32 "
                 "{%0,%1,%2,%3}, {%4,%5,%6,%7}, {%8,%9}, {%0,%1,%2,%3};"
                 : "+f"(c[0]), "+f"(c[1]), "+f"(c[2]), "+f"(c[3])
                 : "r"(a[0]), "r"(a[1]), "r"(a[2]), "r"(a[3]), "r"(b[0]), "r"(b[1]));
}

// ---------------------------------------------------------------------------
// fp32 -> fp16 (RN) bulk convert: 4 elements / thread.
// ---------------------------------------------------------------------------
__global__ void k_cvt(const float4* __restrict__ src, uint2* __restrict__ dst, int n4) {
    int i = blockIdx.x * blockDim.x + threadIdx.x;
    if (i < n4) {
        float4 v = src[i];
        __half2 h0 = __floats2half2_rn(v.x, v.y);
        __half2 h1 = __floats2half2_rn(v.z, v.w);
        dst[i] = make_uint2(*(uint32_t*)&h0, *(uint32_t*)&h1);
    }
}

// ---------------------------------------------------------------------------
__global__ void k_zero(float* __restrict__ out) {
    int i = blockIdx.x * blockDim.x + threadIdx.x;
    float4 z = make_float4(0.f, 0.f, 0.f, 0.f);
    if (i < (NT * DD / 4)) reinterpret_cast<float4*>(out)[i] = z;
    if (i < NE) g_count[i] = 0;
}

// ---------------------------------------------------------------------------
// Router (exact fp32): warp per token, renormalized top-2, scatter.
// ---------------------------------------------------------------------------
__global__ void k_router(const float* __restrict__ x, const float* __restrict__ rw) {
    __shared__ float s_rw[NE * DD];
    const int tid = threadIdx.x;
    for (int i = tid; i < NE * DD; i += 256) s_rw[i] = rw[i];
    __syncthreads();

    const int warp = tid >> 5;
    const int lane = tid & 31;
    const int token = blockIdx.x * 8 + warp;
    const float* xr = x + (size_t)token * DD;

    float acc[NE];
#pragma unroll
    for (int e = 0; e < NE; e++) acc[e] = 0.f;
    for (int d = lane; d < DD; d += 32) {
        float xv = xr[d];
#pragma unroll
        for (int e = 0; e < NE; e++) acc[e] = fmaf(xv, s_rw[e * DD + d], acc[e]);
    }
#pragma unroll
    for (int e = 0; e < NE; e++)
#pragma unroll
        for (int off = 16; off > 0; off >>= 1)
            acc[e] += __shfl_xor_sync(0xffffffffu, acc[e], off);

    if (lane == 0) {
        int i1 = 0;
#pragma unroll
        for (int e = 1; e < NE; e++) if (acc[e] > acc[i1]) i1 = e;
        int i2 = (i1 == 0) ? 1 : 0;
#pragma unroll
        for (int e = 0; e < NE; e++) if (e != i1 && acc[e] > acc[i2]) i2 = e;
        float s  = expf(acc[i2] - acc[i1]);
        float p1 = 1.f / (1.f + s);
        float p2 = s / (1.f + s);
        int s1 = atomicAdd(&g_count[i1], 1);
        g_tok[i1][s1] = token; g_wt[i1][s1] = p1;
        int s2 = atomicAdd(&g_count[i2], 1);
        g_tok[i2][s2] = token; g_wt[i2][s2] = p2;
    }
}

// ---------------------------------------------------------------------------
// Shared tiling constants: smem rows of 32 halves padded to 40 (80B) ->
// 8-row ldmatrix octets land on 8 distinct 16B bank-groups (80*r mod 128 all distinct).
// ---------------------------------------------------------------------------
#define ROWB 80
#define A_TILEB (128 * ROWB)      // 10240 B (128 rows x 32 halves)
#define B64_TILEB (64 * ROWB)     // 5120 B

// ---------------------------------------------------------------------------
// Gate+Up fp16 GEMM: block 128(M) x 64(N); 8 warps: wid<4 gate, wid>=4 up,
// each half a 2x2 grid of 64x32 warp tiles. BK=32 (2 x k16), cp.async double buffer.
// ---------------------------------------------------------------------------
#define GU_STGB (A_TILEB + 2 * B64_TILEB)   // 20480
#define GU_SMEMB (2 * GU_STGB)              // 40960

__global__ __launch_bounds__(256) void k_gateup(void) {
    const int e  = blockIdx.z;
    const int ne = g_count[e];
    const int m0 = blockIdx.y * 128;
    if (m0 >= ne) return;
    const int n0 = blockIdx.x * 64;

    extern __shared__ float sm[];
    const uint32_t sbase = smem_u32(sm);
    const int tid = threadIdx.x, lane = tid & 31, wid = tid >> 5;
    const int half_ = wid >> 2, wq = wid & 3;
    const int wm = (wq >> 1) * 64, wn = (wq & 1) * 32;

    // A loader: 128 rows x 4 chunks(16B) = 512 -> 2/thread (gathered rows).
    const __half* asrc[2]; uint32_t adst[2];
#pragma unroll
    for (int i = 0; i < 2; i++) {
        int c = i * 256 + tid, row = c >> 2, kc = c & 3;
        int gr = m0 + row; if (gr >= ne) gr = ne - 1;  // clamp; rows discarded downstream
        asrc[i] = g_xh + (size_t)g_tok[e][gr] * DD + kc * 8;
        adst[i] = (uint32_t)(row * ROWB + kc * 16);
    }
    // B loaders: 64 rows x 4 chunks = 256 -> 1/thread each for gate and up.
    const __half *gsrc, *usrc; uint32_t bdst;
    {
        int row = tid >> 2, kc = tid & 3;
        size_t off = (size_t)e * HH * DD + (size_t)(n0 + row) * DD + kc * 8;
        gsrc = g_wgh + off; usrc = g_wuh + off;
        bdst = (uint32_t)(row * ROWB + kc * 16);
    }

#define GU_LOAD(buf, kt) do {                                                   \
        uint32_t s0 = sbase + (uint32_t)(buf) * GU_STGB;                        \
        CPA(s0 + adst[0], asrc[0] + (kt) * 32);                                 \
        CPA(s0 + adst[1], asrc[1] + (kt) * 32);                                 \
        CPA(s0 + A_TILEB + bdst, gsrc + (kt) * 32);                             \
        CPA(s0 + A_TILEB + B64_TILEB + bdst, usrc + (kt) * 32);                 \
    } while (0)

    float acc[4][4][4];
#pragma unroll
    for (int mi = 0; mi < 4; mi++)
#pragma unroll
        for (int nj = 0; nj < 4; nj++)
#pragma unroll
            for (int r = 0; r < 4; r++) acc[mi][nj][r] = 0.f;

    const uint32_t a_lrow = lane & 15;
    const uint32_t a_colB = ((lane >> 4) & 1) * 16;
    const uint32_t b_lrow = (lane & 7) + ((lane >> 4) & 1) * 8;
    const uint32_t b_colB = ((lane >> 3) & 1) * 16;

    GU_LOAD(0, 0);
    CPC();
    const int NK = DD / 32;
    for (int t = 0; t < NK; t++) {
        if (t + 1 < NK) { GU_LOAD((t + 1) & 1, t + 1); CPC(); CPW(1); }
        else            { CPW(0); }
        __syncthreads();
        const uint32_t sAq = sbase + (uint32_t)(t & 1) * GU_STGB;
        const uint32_t sBq = sAq + (uint32_t)(A_TILEB + half_ * B64_TILEB);
#pragma unroll
        for (int ks = 0; ks < 2; ks++) {        // 2 x k16 per BK=32 tile
            uint32_t a[4][4], b[4][2];
#pragma unroll
            for (int mi = 0; mi < 4; mi++)
                ldsm4(a[mi][0], a[mi][1], a[mi][2], a[mi][3],
                      sAq + (wm + mi * 16 + a_lrow) * ROWB + ks * 32 + a_colB);
#pragma unroll
            for (int p = 0; p < 2; p++) {
                uint32_t r0, r1, r2, r3;
                ldsm4(r0, r1, r2, r3,
                      sBq + (wn + p * 16 + b_lrow) * ROWB + ks * 32 + b_colB);
                b[2 * p][0] = r0; b[2 * p][1] = r1; b[2 * p + 1][0] = r2; b[2 * p + 1][1] = r3;
            }
#pragma unroll
            for (int mi = 0; mi < 4; mi++)
#pragma unroll
                for (int nj = 0; nj < 4; nj++) mma16(acc[mi][nj], a[mi], b[nj]);
        }
        __syncthreads();
    }
#undef GU_LOAD

    // Epilogue: up warps stage accum in smem (fp32); gate warps combine silu(g)*u -> g_acth (fp16).
    if (half_ == 1) {
#pragma unroll
        for (int mi = 0; mi < 4; mi++)
#pragma unroll
            for (int nj = 0; nj < 4; nj++) {
                int m = wm + mi * 16 + (lane >> 2);
                int n = wn + nj * 8 + (lane & 3) * 2;
                *(float2*)&sm[m * 66 + n]       = make_float2(acc[mi][nj][0], acc[mi][nj][1]);
                *(float2*)&sm[(m + 8) * 66 + n] = make_float2(acc[mi][nj][2], acc[mi][nj][3]);
            }
    }
    __syncthreads();
    if (half_ == 0) {
        __half* actb = g_acth + (size_t)e * NT * HH + (size_t)m0 * HH + n0;
#pragma unroll
        for (int mi = 0; mi < 4; mi++)
#pragma unroll
            for (int nj = 0; nj < 4; nj++) {
                int m = wm + mi * 16 + (lane >> 2);
                int n = wn + nj * 8 + (lane & 3) * 2;
                float2 u0 = *(float2*)&sm[m * 66 + n];
                float2 u1 = *(float2*)&sm[(m + 8) * 66 + n];
                float g0 = acc[mi][nj][0], g1 = acc[mi][nj][1];
                float g2 = acc[mi][nj][2], g3 = acc[mi][nj][3];
                __half2 v0 = __floats2half2_rn(g0 / (1.f + expf(-g0)) * u0.x,
                                               g1 / (1.f + expf(-g1)) * u0.y);
                __half2 v1 = __floats2half2_rn(g2 / (1.f + expf(-g2)) * u1.x,
                                               g3 / (1.f + expf(-g3)) * u1.y);
                *(__half2*)(actb + (size_t)m * HH + n)       = v0;
                *(__half2*)(actb + (size_t)(m + 8) * HH + n) = v1;
            }
    }
}

// ---------------------------------------------------------------------------
// Down fp16 GEMM + weighted scatter: block 128(M) x 128(N), 8 warps 2x4, warp 64x32.
// ---------------------------------------------------------------------------
#define DN_STGB (2 * A_TILEB)     // 20480 (A 128x32 + B 128x32)
#define DN_SMEMB (2 * DN_STGB)    // 40960

__global__ __launch_bounds__(256) void k_down(float* __restrict__ out) {
    const int e  = blockIdx.z;
    const int ne = g_count[e];
    const int m0 = blockIdx.y * 128;
    if (m0 >= ne) return;
    const int n0 = blockIdx.x * 128;

    extern __shared__ float sm[];
    const uint32_t sbase = smem_u32(sm);
    const int tid = threadIdx.x, lane = tid & 31, wid = tid >> 5;
    const int wm = (wid >> 2) * 64, wn = (wid & 3) * 32;

    const __half *asrc[2], *bsrc[2]; uint32_t cdst[2];
#pragma unroll
    for (int i = 0; i < 2; i++) {
        int c = i * 256 + tid, row = c >> 2, kc = c & 3;
        asrc[i] = g_acth + (size_t)e * NT * HH + (size_t)(m0 + row) * HH + kc * 8;
        bsrc[i] = g_wdh + (size_t)e * DD * HH + (size_t)(n0 + row) * HH + kc * 8;
        cdst[i] = (uint32_t)(row * ROWB + kc * 16);
    }

#define DN_LOAD(buf, kt) do {                                                   \
        uint32_t s0 = sbase + (uint32_t)(buf) * DN_STGB;                        \
        CPA(s0 + cdst[0], asrc[0] + (kt) * 32);                                 \
        CPA(s0 + cdst[1], asrc[1] + (kt) * 32);                                 \
        CPA(s0 + A_TILEB + cdst[0], bsrc[0] + (kt) * 32);                       \
        CPA(s0 + A_TILEB + cdst[1], bsrc[1] + (kt) * 32);                       \
    } while (0)

    float acc[4][4][4];
#pragma unroll
    for (int mi = 0; mi < 4; mi++)
#pragma unroll
        for (int nj = 0; nj < 4; nj++)
#pragma unroll
            for (int r = 0; r < 4; r++) acc[mi][nj][r] = 0.f;

    const uint32_t a_lrow = lane & 15;
    const uint32_t a_colB = ((lane >> 4) & 1) * 16;
    const uint32_t b_lrow = (lane & 7) + ((lane >> 4) & 1) * 8;
    const uint32_t b_colB = ((lane >> 3) & 1) * 16;

    DN_LOAD(0, 0);
    CPC();
    const int NK = HH / 32;
    for (int t = 0; t < NK; t++) {
        if (t + 1 < NK) { DN_LOAD((t + 1) & 1, t + 1); CPC(); CPW(1); }
        else            { CPW(0); }
        __syncthreads();
        const uint32_t sAq = sbase + (uint32_t)(t & 1) * DN_STGB;
        const uint32_t sBq = sAq + A_TILEB;
#pragma unroll
        for (int ks = 0; ks < 2; ks++) {
            uint32_t a[4][4], b[4][2];
#pragma unroll
            for (int mi = 0; mi < 4; mi++)
                ldsm4(a[mi][0], a[mi][1], a[mi][2], a[mi][3],
                      sAq + (wm + mi * 16 + a_lrow) * ROWB + ks * 32 + a_colB);
#pragma unroll
            for (int p = 0; p < 2; p++) {
                uint32_t r0, r1, r2, r3;
                ldsm4(r0, r1, r2, r3,
                      sBq + (wn + p * 16 + b_lrow) * ROWB + ks * 32 + b_colB);
                b[2 * p][0] = r0; b[2 * p][1] = r1; b[2 * p + 1][0] = r2; b[2 * p + 1][1] = r3;
            }
#pragma unroll
            for (int mi = 0; mi < 4; mi++)
#pragma unroll
                for (int nj = 0; nj < 4; nj++) mma16(acc[mi][nj], a[mi], b[nj]);
        }
        __syncthreads();
    }
#undef DN_LOAD

    // Weighted atomic scatter (each out element gets exactly 2 commutative adds).
#pragma unroll
    for (int mi = 0; mi < 4; mi++) {
        int mg0 = m0 + wm + mi * 16 + (lane >> 2);
        int mg1 = mg0 + 8;
        bool v0 = mg0 < ne, v1 = mg1 < ne;
        int   t0 = v0 ? g_tok[e][mg0] : 0;  float w0 = v0 ? g_wt[e][mg0] : 0.f;
        int   t1 = v1 ? g_tok[e][mg1] : 0;  float w1 = v1 ? g_wt[e][mg1] : 0.f;
        float* r0p = out + (size_t)t0 * DD;
        float* r1p = out + (size_t)t1 * DD;
#pragma unroll
        for (int nj = 0; nj < 4; nj++) {
            int n = n0 + wn + nj * 8 + (lane & 3) * 2;
            if (v0) {
                atomicAdd(r0p + n,     w0 * acc[mi][nj][0]);
                atomicAdd(r0p + n + 1, w0 * acc[mi][nj][1]);
            }
            if (v1) {
                atomicAdd(r1p + n,     w1 * acc[mi][nj][2]);
                atomicAdd(r1p + n + 1, w1 * acc[mi][nj][3]);
            }
        }
    }
}

// ---------------------------------------------------------------------------
extern "C" void kernel_launch(void* const* d_in, const int* in_sizes, int n_in,
                              void* d_out, int out_size) {
    const float* x  = (const float*)d_in[0];  // [4,2048,1024]
    const float* rw = (const float*)d_in[1];  // [8,1024]
    const float* gw = (const float*)d_in[2];  // [8,2048,1024]
    const float* uw = (const float*)d_in[3];  // [8,2048,1024]
    const float* dw = (const float*)d_in[4];  // [8,1024,2048]
    float* out = (float*)d_out;               // [4,2048,1024]

    cudaFuncSetAttribute(k_gateup, cudaFuncAttributeMaxDynamicSharedMemorySize, GU_SMEMB);
    cudaFuncSetAttribute(k_down,   cudaFuncAttributeMaxDynamicSharedMemorySize, DN_SMEMB);

    __half *xh, *wgh, *wuh, *wdh;
    cudaGetSymbolAddress((void**)&xh,  g_xh);
    cudaGetSymbolAddress((void**)&wgh, g_wgh);
    cudaGetSymbolAddress((void**)&wuh, g_wuh);
    cudaGetSymbolAddress((void**)&wdh, g_wdh);

    const int nx4 = NT * DD / 4;            // 2,097,152
    const int nw4 = NE * HH * DD / 4;       // 4,194,304
    k_cvt<<<(nx4 + 255) / 256, 256>>>((const float4*)x,  (uint2*)xh,  nx4);
    k_cvt<<<(nw4 + 255) / 256, 256>>>((const float4*)gw, (uint2*)wgh, nw4);
    k_cvt<<<(nw4 + 255) / 256, 256>>>((const float4*)uw, (uint2*)wuh, nw4);
    k_cvt<<<(nw4 + 255) / 256, 256>>>((const float4*)dw, (uint2*)wdh, nw4);

    k_zero<<<(NT * DD / 4 + 255) / 256, 256>>>(out);
    k_router<<<NT / 8, 256>>>(x, rw);
    k_gateup<<<dim3(HH / 64, NT / 128, NE), 256, GU_SMEMB>>>();
    k_down<<<dim3(DD / 128, NT / 128, NE), 256, DN_SMEMB>>>(out);
}